// round 15
// baseline (speedup 1.0000x reference)
#include <cuda_runtime.h>
#include <stdint.h>

#define N_MAXN 150000
#define E_MAXE 2400000
#define F_IN 22
#define HID 32
#define N_CLS 6
#define BN_EPS 1e-5f
#define MAXDEG 64
typedef unsigned long long ull;

// ---------------- packed f32x2 helpers (sm_100a) ----------------
__device__ __forceinline__ ull pack2(float lo, float hi) {
    ull r; asm("mov.b64 %0, {%1, %2};" : "=l"(r) : "f"(lo), "f"(hi)); return r;
}
__device__ __forceinline__ void unpack2(ull v, float& lo, float& hi) {
    asm("mov.b64 {%0, %1}, %2;" : "=f"(lo), "=f"(hi) : "l"(v));
}
__device__ __forceinline__ ull fma2(ull a, ull b, ull c) {
    ull d; asm("fma.rn.f32x2 %0, %1, %2, %3;" : "=l"(d) : "l"(a), "l"(b), "l"(c)); return d;
}
__device__ __forceinline__ ull add2(ull a, ull b) {
    ull d; asm("add.rn.f32x2 %0, %1, %2;" : "=l"(d) : "l"(a), "l"(b)); return d;
}

// ---------------- device scratch (no allocations allowed) ----------------
__device__ __align__(16) float g_hs[N_MAXN * HID];
__device__ __align__(16) float g_agg[N_MAXN * HID];
__device__ int   g_cnt[N_MAXN];
__device__ int   g_pad[(size_t)N_MAXN * MAXDEG];
__device__ float g_sum[HID];
__device__ float g_sumsq[HID];
__device__ int   g_is64;

// ---------------- zero counters + BN accum + dtype detection ----------------
__global__ void k_zero(const long long* __restrict__ ei, int n) {
    int i = blockIdx.x * blockDim.x + threadIdx.x;
    if (i < n) g_cnt[i] = 0;
    if (i < HID) { g_sum[i] = 0.0f; g_sumsq[i] = 0.0f; }
    if (blockIdx.x == 0 && threadIdx.x < 32) {
        int t = threadIdx.x;
        long long v0 = ei[t];
        long long v1 = ei[t + 32];
        int bad = (v0 < 0) | (v0 >= (long long)n) | (v1 < 0) | (v1 >= (long long)n);
        unsigned m = __ballot_sync(0xffffffffu, bad);
        if (t == 0) g_is64 = (m == 0u);
    }
}

// ---------------- fused build (4 edges/thread) + MLP (1 node/thread) ----------------
__global__ void __launch_bounds__(256)
k_fused(const float* __restrict__ x, const float* __restrict__ Wemb,
        const float* __restrict__ bemb, const float* __restrict__ Wgcn,
        const void* __restrict__ ei, int e, int n, int buildBlocks) {
    if ((int)blockIdx.x < buildBlocks) {
        int i = blockIdx.x * 256 + threadIdx.x;
        int quads = e >> 2;
        if (i >= quads) return;
        int s[4], d[4];
        if (g_is64) {
            const longlong2* p = (const longlong2*)ei;
            longlong2 sv0 = p[2 * i], sv1 = p[2 * i + 1];
            const longlong2* pd = p + ((size_t)e >> 1);
            longlong2 dv0 = pd[2 * i], dv1 = pd[2 * i + 1];
            s[0] = (int)sv0.x; s[1] = (int)sv0.y; s[2] = (int)sv1.x; s[3] = (int)sv1.y;
            d[0] = (int)dv0.x; d[1] = (int)dv0.y; d[2] = (int)dv1.x; d[3] = (int)dv1.y;
        } else {
            const int4* p = (const int4*)ei;
            int4 sv = p[i];
            int4 dv = p[(size_t)(e >> 2) + i];
            s[0] = sv.x; s[1] = sv.y; s[2] = sv.z; s[3] = sv.w;
            d[0] = dv.x; d[1] = dv.y; d[2] = dv.z; d[3] = dv.w;
        }
#pragma unroll
        for (int k = 0; k < 4; k++) {
            int pos = atomicAdd(&g_cnt[d[k]], 1);
            if (pos < MAXDEG) g_pad[(size_t)d[k] * MAXDEG + pos] = s[k];
        }
        return;
    }

    // ---- mlp role ----
    __shared__ __align__(16) float sWeT[HID * 24];
    __shared__ float sb[HID];
    __shared__ __align__(16) float sWg[HID * HID];
    for (int i = threadIdx.x; i < F_IN * HID; i += 256) {
        int k = i / HID, j = i % HID;
        sWeT[j * 24 + k] = Wemb[i];
    }
    for (int i = threadIdx.x; i < HID; i += 256) {
        sWeT[i * 24 + 22] = 0.0f;
        sWeT[i * 24 + 23] = 0.0f;
    }
    for (int i = threadIdx.x; i < HID * HID; i += 256) sWg[i] = Wgcn[i];
    if (threadIdx.x < HID) sb[threadIdx.x] = bemb[threadIdx.x];
    __syncthreads();

    int node = ((int)blockIdx.x - buildBlocks) * 256 + threadIdx.x;
    if (node >= n) return;

    float xr[F_IN];
    const float* xp = x + (size_t)node * F_IN;
#pragma unroll
    for (int k = 0; k < F_IN; k++) xr[k] = xp[k];
    ull xx[11];
#pragma unroll
    for (int q = 0; q < 11; q++) xx[q] = pack2(xr[2*q], xr[2*q+1]);

    ull acc2[16];
#pragma unroll
    for (int q = 0; q < 16; q++) acc2[q] = 0ull;

    for (int j = 0; j < HID; j++) {
        const ulonglong2* wr = (const ulonglong2*)(sWeT + j * 24);
        ulonglong2 wA = wr[0], wB = wr[1], wC = wr[2];
        ulonglong2 wD = wr[3], wE = wr[4], wF = wr[5];
        ull ta = fma2(xx[0], wA.x, 0ull);
        ull tb = fma2(xx[4], wC.x, 0ull);
        ull tc = fma2(xx[8], wE.x, 0ull);
        ta = fma2(xx[1], wA.y, ta);
        tb = fma2(xx[5], wC.y, tb);
        tc = fma2(xx[9], wE.y, tc);
        ta = fma2(xx[2], wB.x, ta);
        tb = fma2(xx[6], wD.x, tb);
        tc = fma2(xx[10], wF.x, tc);
        ta = fma2(xx[3], wB.y, ta);
        tb = fma2(xx[7], wD.y, tb);
        ull ts = add2(add2(ta, tb), tc);
        float lo, hi; unpack2(ts, lo, hi);
        float t = fmaxf(lo + hi + sb[j], 0.0f);
        ull tt = pack2(t, t);
        const ulonglong2* gr = (const ulonglong2*)(sWg + j * HID);
#pragma unroll
        for (int q = 0; q < 8; q++) {
            ulonglong2 g = gr[q];
            acc2[2*q]   = fma2(tt, g.x, acc2[2*q]);
            acc2[2*q+1] = fma2(tt, g.y, acc2[2*q+1]);
        }
    }

    float* hp = g_hs + (size_t)node * HID;
#pragma unroll
    for (int q = 0; q < 8; q++) {
        float a, b, c, d;
        unpack2(acc2[2*q], a, b);
        unpack2(acc2[2*q+1], c, d);
        ((float4*)hp)[q] = make_float4(a, b, c, d);
    }
}

// tail: leftover e % 4 edges
__global__ void k_build_tail(const void* __restrict__ ei, int e, int r) {
    int k = threadIdx.x;
    if (k >= r) return;
    int i = e - 1 - k;
    int s, d;
    if (g_is64) {
        const long long* p = (const long long*)ei;
        s = (int)p[i]; d = (int)p[(size_t)e + i];
    } else {
        const int* p = (const int*)ei;
        s = p[i]; d = p[(size_t)e + i];
    }
    int pos = atomicAdd(&g_cnt[d], 1);
    if (pos < MAXDEG) g_pad[(size_t)d * MAXDEG + pos] = s;
}

// ---------------- scale: hs *= dis ----------------
__global__ void __launch_bounds__(256)
k_scale(int n) {
    int t = blockIdx.x * 256 + threadIdx.x;
    if (t >= n * 8) return;
    int node = t >> 3;
    int q = t & 7;
    float dis = rsqrtf((float)g_cnt[node] + 1.0f);
    float4* p = (float4*)g_hs + (size_t)node * 8 + q;
    float4 v = *p;
    v.x *= dis; v.y *= dis; v.z *= dis; v.w *= dis;
    *p = v;
}

// ---------------- gather: 4 nodes/warp, preloaded index regs ----------------
// All adjacency indices for slots 0..31 preloaded into 4 regs (parallel LDGs)
// so the chunk loops have NO loads feeding shuffles. Slots >= m never
// dereferenced (predicated), so stale index values are safe.
__global__ void __launch_bounds__(256)
k_gather(const float* __restrict__ bgcn, int n) {
    int warp = (blockIdx.x * 256 + threadIdx.x) >> 5;
    int lane = threadIdx.x & 31;
    int g = lane >> 3;           // group = node within warp
    int q = lane & 7;            // 16B feature slot
    int node = warp * 4 + g;
    bool valid = node < n;
    int nodec = valid ? node : (n - 1);

    int cnt = g_cnt[nodec];
    float dis = rsqrtf((float)cnt + 1.0f);
    int m = valid ? min(cnt, MAXDEG) : 0;

    const int* row = g_pad + (size_t)nodec * MAXDEG;
    // preload indices for slots 0..31 (4 parallel LDGs)
    int i0 = row[q];
    int i1 = row[8 + q];
    int i2 = row[16 + q];
    int i3 = row[24 + q];

    float4 acc = make_float4(0.0f, 0.0f, 0.0f, 0.0f);
    if (valid) acc = ((const float4*)(g_hs + (size_t)nodec * HID))[q];

    // warp-max degree
    int mmax = m;
#pragma unroll
    for (int o = 16; o; o >>= 1) mmax = max(mmax, __shfl_xor_sync(0xffffffffu, mmax, o));

    int grpbase = lane & 24;     // g*8

#define PROC8(IREG, BASE)                                                     \
    {                                                                          \
        _Pragma("unroll")                                                      \
        for (int k = 0; k < 8; k++) {                                          \
            int s = __shfl_sync(0xffffffffu, IREG, grpbase | k);               \
            if ((BASE) + k < m) {                                              \
                float4 v = ((const float4*)(g_hs + (size_t)s * HID))[q];       \
                acc.x += v.x; acc.y += v.y; acc.z += v.z; acc.w += v.w;        \
            }                                                                  \
        }                                                                      \
    }

    PROC8(i0, 0);
    if (mmax > 8)  PROC8(i1, 8);
    if (mmax > 16) PROC8(i2, 16);
    if (mmax > 24) PROC8(i3, 24);
    if (mmax > 32) {             // rare high-degree phase
        int i4 = row[32 + q];
        int i5 = row[40 + q];
        int i6 = row[48 + q];
        int i7 = row[56 + q];
        PROC8(i4, 32);
        if (mmax > 40) PROC8(i5, 40);
        if (mmax > 48) PROC8(i6, 48);
        if (mmax > 56) PROC8(i7, 56);
    }
#undef PROC8

    if (valid) {
        float4 bg = ((const float4*)bgcn)[q];
        float4 o;
        o.x = fmaf(dis, acc.x, bg.x);
        o.y = fmaf(dis, acc.y, bg.y);
        o.z = fmaf(dis, acc.z, bg.z);
        o.w = fmaf(dis, acc.w, bg.w);
        ((float4*)(g_agg + (size_t)node * HID))[q] = o;
    }
}

// ---------------- BN statistics: per-column sum / sumsq ----------------
__global__ void __launch_bounds__(256)
k_bnsum(int n) {
    int col = threadIdx.x & 31;
    float s = 0.0f, s2 = 0.0f;
    int total = n * HID;
    int stride = gridDim.x * blockDim.x;
    for (int idx = blockIdx.x * blockDim.x + threadIdx.x; idx < total; idx += stride) {
        float v = g_agg[idx];
        s += v;
        s2 = fmaf(v, v, s2);
    }
    __shared__ float sh[2][8][32];
    int w = threadIdx.x >> 5;
    sh[0][w][col] = s;
    sh[1][w][col] = s2;
    __syncthreads();
    if (threadIdx.x < 32) {
        float ts = 0.0f, t2 = 0.0f;
#pragma unroll
        for (int i = 0; i < 8; i++) { ts += sh[0][i][col]; t2 += sh[1][i][col]; }
        atomicAdd(&g_sum[col], ts);
        atomicAdd(&g_sumsq[col], t2);
    }
}

// ---------------- classifier with inlined BN finalize ----------------
__global__ void __launch_bounds__(128)
k_cls(const float* __restrict__ gamma, const float* __restrict__ beta,
      const float* __restrict__ Wcls, const float* __restrict__ bcls,
      float* __restrict__ out, int n) {
    __shared__ float sW[HID * N_CLS];
    __shared__ float sbc[N_CLS];
    __shared__ float ssc[HID];
    __shared__ float ssh[HID];
    for (int i = threadIdx.x; i < HID * N_CLS; i += blockDim.x) sW[i] = Wcls[i];
    if (threadIdx.x < N_CLS) sbc[threadIdx.x] = bcls[threadIdx.x];
    if (threadIdx.x < HID) {
        int c = threadIdx.x;
        float inv_n = 1.0f / (float)n;
        float mean = g_sum[c] * inv_n;
        float var = g_sumsq[c] * inv_n - mean * mean;
        float sc = gamma[c] * rsqrtf(var + BN_EPS);
        ssc[c] = sc;
        ssh[c] = beta[c] - mean * sc;
    }
    __syncthreads();

    int node = blockIdx.x * blockDim.x + threadIdx.x;
    if (node >= n) return;

    float acc[N_CLS];
#pragma unroll
    for (int c = 0; c < N_CLS; c++) acc[c] = sbc[c];

    const float4* ap = (const float4*)(g_agg + (size_t)node * HID);
#pragma unroll
    for (int qq = 0; qq < HID / 4; qq++) {
        float4 v4 = ap[qq];
        float vv[4] = {v4.x, v4.y, v4.z, v4.w};
#pragma unroll
        for (int u = 0; u < 4; u++) {
            int j = qq * 4 + u;
            float v = fmaxf(fmaf(vv[u], ssc[j], ssh[j]), 0.0f);
#pragma unroll
            for (int c = 0; c < N_CLS; c++) acc[c] = fmaf(v, sW[j * N_CLS + c], acc[c]);
        }
    }
    float* op = out + (size_t)node * N_CLS;
#pragma unroll
    for (int c = 0; c < N_CLS; c++) op[c] = acc[c];
}

// ---------------- launch ----------------
extern "C" void kernel_launch(void* const* d_in, const int* in_sizes, int n_in,
                              void* d_out, int out_size) {
    const float* x     = (const float*)d_in[0];
    const void*  ei    = d_in[1];
    const float* Wemb  = (const float*)d_in[2];
    const float* bemb  = (const float*)d_in[3];
    const float* Wgcn  = (const float*)d_in[4];
    const float* bgcn  = (const float*)d_in[5];
    const float* gamma = (const float*)d_in[6];
    const float* beta  = (const float*)d_in[7];
    const float* Wcls  = (const float*)d_in[8];
    const float* bcls  = (const float*)d_in[9];
    float* out = (float*)d_out;

    int n = in_sizes[0] / F_IN;      // 150000
    int e = in_sizes[1] / 2;         // 2400000

    k_zero<<<(n + 255) / 256, 256>>>((const long long*)ei, n);

    int quads = e >> 2;
    int buildBlocks = (quads + 255) / 256;
    int mlpBlocks = (n + 255) / 256;
    k_fused<<<buildBlocks + mlpBlocks, 256>>>(x, Wemb, bemb, Wgcn, ei, e, n, buildBlocks);
    if (e & 3) k_build_tail<<<1, 32>>>(ei, e, e & 3);

    k_scale<<<(n * 8 + 255) / 256, 256>>>(n);
    {
        int warps = (n + 3) / 4;
        k_gather<<<(warps * 32 + 255) / 256, 256>>>(bgcn, n);
    }
    k_bnsum<<<2048, 256>>>(n);
    k_cls<<<(n + 127) / 128, 128>>>(gamma, beta, Wcls, bcls, out, n);
}

// round 16
// speedup vs baseline: 1.0718x; 1.0718x over previous
#include <cuda_runtime.h>
#include <stdint.h>

#define N_MAXN 150000
#define E_MAXE 2400000
#define F_IN 22
#define HID 32
#define N_CLS 6
#define BN_EPS 1e-5f
#define MAXDEG 64
typedef unsigned long long ull;

// ---------------- packed f32x2 helpers (sm_100a) ----------------
__device__ __forceinline__ ull pack2(float lo, float hi) {
    ull r; asm("mov.b64 %0, {%1, %2};" : "=l"(r) : "f"(lo), "f"(hi)); return r;
}
__device__ __forceinline__ void unpack2(ull v, float& lo, float& hi) {
    asm("mov.b64 {%0, %1}, %2;" : "=f"(lo), "=f"(hi) : "l"(v));
}
__device__ __forceinline__ ull fma2(ull a, ull b, ull c) {
    ull d; asm("fma.rn.f32x2 %0, %1, %2, %3;" : "=l"(d) : "l"(a), "l"(b), "l"(c)); return d;
}
__device__ __forceinline__ ull add2(ull a, ull b) {
    ull d; asm("add.rn.f32x2 %0, %1, %2;" : "=l"(d) : "l"(a), "l"(b)); return d;
}

// ---------------- device scratch (no allocations allowed) ----------------
__device__ __align__(16) float g_hs[N_MAXN * HID];
__device__ __align__(16) float g_agg[N_MAXN * HID];
__device__ int   g_cnt[N_MAXN];
__device__ int   g_pad[(size_t)N_MAXN * MAXDEG];
__device__ float g_sum[HID];
__device__ float g_sumsq[HID];
__device__ int   g_is64;

// ---------------- zero counters + BN accum + dtype detection ----------------
__global__ void k_zero(const long long* __restrict__ ei, int n) {
    int i = blockIdx.x * blockDim.x + threadIdx.x;
    if (i < n) g_cnt[i] = 0;
    if (i < HID) { g_sum[i] = 0.0f; g_sumsq[i] = 0.0f; }
    if (blockIdx.x == 0 && threadIdx.x < 32) {
        int t = threadIdx.x;
        long long v0 = ei[t];
        long long v1 = ei[t + 32];
        int bad = (v0 < 0) | (v0 >= (long long)n) | (v1 < 0) | (v1 >= (long long)n);
        unsigned m = __ballot_sync(0xffffffffu, bad);
        if (t == 0) g_is64 = (m == 0u);
    }
}

// ---------------- fused build (4 edges/thread) + MLP (1 node/thread) ----------------
__global__ void __launch_bounds__(256)
k_fused(const float* __restrict__ x, const float* __restrict__ Wemb,
        const float* __restrict__ bemb, const float* __restrict__ Wgcn,
        const void* __restrict__ ei, int e, int n, int buildBlocks) {
    if ((int)blockIdx.x < buildBlocks) {
        int i = blockIdx.x * 256 + threadIdx.x;
        int quads = e >> 2;
        if (i >= quads) return;
        int s[4], d[4];
        if (g_is64) {
            const longlong2* p = (const longlong2*)ei;
            longlong2 sv0 = p[2 * i], sv1 = p[2 * i + 1];
            const longlong2* pd = p + ((size_t)e >> 1);
            longlong2 dv0 = pd[2 * i], dv1 = pd[2 * i + 1];
            s[0] = (int)sv0.x; s[1] = (int)sv0.y; s[2] = (int)sv1.x; s[3] = (int)sv1.y;
            d[0] = (int)dv0.x; d[1] = (int)dv0.y; d[2] = (int)dv1.x; d[3] = (int)dv1.y;
        } else {
            const int4* p = (const int4*)ei;
            int4 sv = p[i];
            int4 dv = p[(size_t)(e >> 2) + i];
            s[0] = sv.x; s[1] = sv.y; s[2] = sv.z; s[3] = sv.w;
            d[0] = dv.x; d[1] = dv.y; d[2] = dv.z; d[3] = dv.w;
        }
#pragma unroll
        for (int k = 0; k < 4; k++) {
            int pos = atomicAdd(&g_cnt[d[k]], 1);
            if (pos < MAXDEG) g_pad[(size_t)d[k] * MAXDEG + pos] = s[k];
        }
        return;
    }

    // ---- mlp role ----
    __shared__ __align__(16) float sWeT[HID * 24];
    __shared__ float sb[HID];
    __shared__ __align__(16) float sWg[HID * HID];
    for (int i = threadIdx.x; i < F_IN * HID; i += 256) {
        int k = i / HID, j = i % HID;
        sWeT[j * 24 + k] = Wemb[i];
    }
    for (int i = threadIdx.x; i < HID; i += 256) {
        sWeT[i * 24 + 22] = 0.0f;
        sWeT[i * 24 + 23] = 0.0f;
    }
    for (int i = threadIdx.x; i < HID * HID; i += 256) sWg[i] = Wgcn[i];
    if (threadIdx.x < HID) sb[threadIdx.x] = bemb[threadIdx.x];
    __syncthreads();

    int node = ((int)blockIdx.x - buildBlocks) * 256 + threadIdx.x;
    if (node >= n) return;

    float xr[F_IN];
    const float* xp = x + (size_t)node * F_IN;
#pragma unroll
    for (int k = 0; k < F_IN; k++) xr[k] = xp[k];
    ull xx[11];
#pragma unroll
    for (int q = 0; q < 11; q++) xx[q] = pack2(xr[2*q], xr[2*q+1]);

    ull acc2[16];
#pragma unroll
    for (int q = 0; q < 16; q++) acc2[q] = 0ull;

    for (int j = 0; j < HID; j++) {
        const ulonglong2* wr = (const ulonglong2*)(sWeT + j * 24);
        ulonglong2 wA = wr[0], wB = wr[1], wC = wr[2];
        ulonglong2 wD = wr[3], wE = wr[4], wF = wr[5];
        ull ta = fma2(xx[0], wA.x, 0ull);
        ull tb = fma2(xx[4], wC.x, 0ull);
        ull tc = fma2(xx[8], wE.x, 0ull);
        ta = fma2(xx[1], wA.y, ta);
        tb = fma2(xx[5], wC.y, tb);
        tc = fma2(xx[9], wE.y, tc);
        ta = fma2(xx[2], wB.x, ta);
        tb = fma2(xx[6], wD.x, tb);
        tc = fma2(xx[10], wF.x, tc);
        ta = fma2(xx[3], wB.y, ta);
        tb = fma2(xx[7], wD.y, tb);
        ull ts = add2(add2(ta, tb), tc);
        float lo, hi; unpack2(ts, lo, hi);
        float t = fmaxf(lo + hi + sb[j], 0.0f);
        ull tt = pack2(t, t);
        const ulonglong2* gr = (const ulonglong2*)(sWg + j * HID);
#pragma unroll
        for (int q = 0; q < 8; q++) {
            ulonglong2 g = gr[q];
            acc2[2*q]   = fma2(tt, g.x, acc2[2*q]);
            acc2[2*q+1] = fma2(tt, g.y, acc2[2*q+1]);
        }
    }

    float* hp = g_hs + (size_t)node * HID;
#pragma unroll
    for (int q = 0; q < 8; q++) {
        float a, b, c, d;
        unpack2(acc2[2*q], a, b);
        unpack2(acc2[2*q+1], c, d);
        ((float4*)hp)[q] = make_float4(a, b, c, d);
    }
}

// tail: leftover e % 4 edges
__global__ void k_build_tail(const void* __restrict__ ei, int e, int r) {
    int k = threadIdx.x;
    if (k >= r) return;
    int i = e - 1 - k;
    int s, d;
    if (g_is64) {
        const long long* p = (const long long*)ei;
        s = (int)p[i]; d = (int)p[(size_t)e + i];
    } else {
        const int* p = (const int*)ei;
        s = p[i]; d = p[(size_t)e + i];
    }
    int pos = atomicAdd(&g_cnt[d], 1);
    if (pos < MAXDEG) g_pad[(size_t)d * MAXDEG + pos] = s;
}

// ---------------- scale: hs *= dis ----------------
__global__ void __launch_bounds__(256)
k_scale(int n) {
    int t = blockIdx.x * 256 + threadIdx.x;
    if (t >= n * 8) return;
    int node = t >> 3;
    int q = t & 7;
    float dis = rsqrtf((float)g_cnt[node] + 1.0f);
    float4* p = (float4*)g_hs + (size_t)node * 8 + q;
    float4 v = *p;
    v.x *= dis; v.y *= dis; v.z *= dis; v.w *= dis;
    *p = v;
}

// ---------------- gather (R14 loop) + fused BN partial sums ----------------
__global__ void __launch_bounds__(256, 7)
k_gather(const float* __restrict__ bgcn, int n) {
    int warp = (blockIdx.x * 256 + threadIdx.x) >> 5;
    int lane = threadIdx.x & 31;
    int g = lane >> 3;           // group = node within warp
    int q = lane & 7;            // 16B feature slot
    int node = warp * 4 + g;
    bool valid = node < n;
    int nodec = valid ? node : (n - 1);

    int cnt = g_cnt[nodec];
    float dis = rsqrtf((float)cnt + 1.0f);
    int m = valid ? min(cnt, MAXDEG) : 0;

    const int* row = g_pad + (size_t)nodec * MAXDEG;

    float4 acc = make_float4(0.0f, 0.0f, 0.0f, 0.0f);
    if (valid) acc = ((const float4*)(g_hs + (size_t)nodec * HID))[q];

    // warp-max degree
    int mmax = m;
#pragma unroll
    for (int o = 16; o; o >>= 1) mmax = max(mmax, __shfl_xor_sync(0xffffffffu, mmax, o));

    int grpbase = lane & 24;     // g*8
    int idx = 0;
    for (int j = 0; j < mmax; j += 4) {
        if ((j & 7) == 0) idx = row[j + q];   // in-bounds; value guarded at use
        int sA = __shfl_sync(0xffffffffu, idx, grpbase | ((j    ) & 7));
        int sB = __shfl_sync(0xffffffffu, idx, grpbase | ((j + 1) & 7));
        int sC = __shfl_sync(0xffffffffu, idx, grpbase | ((j + 2) & 7));
        int sD = __shfl_sync(0xffffffffu, idx, grpbase | ((j + 3) & 7));
        if (j < m) {
            float4 v = ((const float4*)(g_hs + (size_t)sA * HID))[q];
            acc.x += v.x; acc.y += v.y; acc.z += v.z; acc.w += v.w;
        }
        if (j + 1 < m) {
            float4 v = ((const float4*)(g_hs + (size_t)sB * HID))[q];
            acc.x += v.x; acc.y += v.y; acc.z += v.z; acc.w += v.w;
        }
        if (j + 2 < m) {
            float4 v = ((const float4*)(g_hs + (size_t)sC * HID))[q];
            acc.x += v.x; acc.y += v.y; acc.z += v.z; acc.w += v.w;
        }
        if (j + 3 < m) {
            float4 v = ((const float4*)(g_hs + (size_t)sD * HID))[q];
            acc.x += v.x; acc.y += v.y; acc.z += v.z; acc.w += v.w;
        }
    }

    float4 o = make_float4(0.0f, 0.0f, 0.0f, 0.0f);
    if (valid) {
        float4 bg = ((const float4*)bgcn)[q];
        o.x = fmaf(dis, acc.x, bg.x);
        o.y = fmaf(dis, acc.y, bg.y);
        o.z = fmaf(dis, acc.z, bg.z);
        o.w = fmaf(dis, acc.w, bg.w);
        ((float4*)(g_agg + (size_t)node * HID))[q] = o;
    }

    // ---- fused BN partial reduction ----
    // lane (wid, lane) holds cols 4q..4q+3 of its node; linear smem layout
    // shs[w*128 + g*32 + c] so reduction threads read stride-1 by column.
    __shared__ float shs[8 * 128];
    __shared__ float shq[8 * 128];
    int wid = threadIdx.x >> 5;
    int base = wid * 128 + g * 32 + q * 4;
    shs[base + 0] = o.x; shs[base + 1] = o.y;
    shs[base + 2] = o.z; shs[base + 3] = o.w;
    shq[base + 0] = o.x * o.x; shq[base + 1] = o.y * o.y;
    shq[base + 2] = o.z * o.z; shq[base + 3] = o.w * o.w;
    __syncthreads();
    int t = threadIdx.x;
    if (t < 32) {
        float s = 0.0f;
#pragma unroll
        for (int w = 0; w < 8; w++) {
            s += shs[w * 128 +  0 + t] + shs[w * 128 + 32 + t]
               + shs[w * 128 + 64 + t] + shs[w * 128 + 96 + t];
        }
        atomicAdd(&g_sum[t], s);
    } else if (t < 64) {
        int c = t - 32;
        float s = 0.0f;
#pragma unroll
        for (int w = 0; w < 8; w++) {
            s += shq[w * 128 +  0 + c] + shq[w * 128 + 32 + c]
               + shq[w * 128 + 64 + c] + shq[w * 128 + 96 + c];
        }
        atomicAdd(&g_sumsq[c], s);
    }
}

// ---------------- classifier with inlined BN finalize ----------------
__global__ void __launch_bounds__(128)
k_cls(const float* __restrict__ gamma, const float* __restrict__ beta,
      const float* __restrict__ Wcls, const float* __restrict__ bcls,
      float* __restrict__ out, int n) {
    __shared__ float sW[HID * N_CLS];
    __shared__ float sbc[N_CLS];
    __shared__ float ssc[HID];
    __shared__ float ssh[HID];
    for (int i = threadIdx.x; i < HID * N_CLS; i += blockDim.x) sW[i] = Wcls[i];
    if (threadIdx.x < N_CLS) sbc[threadIdx.x] = bcls[threadIdx.x];
    if (threadIdx.x < HID) {
        int c = threadIdx.x;
        float inv_n = 1.0f / (float)n;
        float mean = g_sum[c] * inv_n;
        float var = g_sumsq[c] * inv_n - mean * mean;
        float sc = gamma[c] * rsqrtf(var + BN_EPS);
        ssc[c] = sc;
        ssh[c] = beta[c] - mean * sc;
    }
    __syncthreads();

    int node = blockIdx.x * blockDim.x + threadIdx.x;
    if (node >= n) return;

    float acc[N_CLS];
#pragma unroll
    for (int c = 0; c < N_CLS; c++) acc[c] = sbc[c];

    const float4* ap = (const float4*)(g_agg + (size_t)node * HID);
#pragma unroll
    for (int qq = 0; qq < HID / 4; qq++) {
        float4 v4 = ap[qq];
        float vv[4] = {v4.x, v4.y, v4.z, v4.w};
#pragma unroll
        for (int u = 0; u < 4; u++) {
            int j = qq * 4 + u;
            float v = fmaxf(fmaf(vv[u], ssc[j], ssh[j]), 0.0f);
#pragma unroll
            for (int c = 0; c < N_CLS; c++) acc[c] = fmaf(v, sW[j * N_CLS + c], acc[c]);
        }
    }
    float* op = out + (size_t)node * N_CLS;
#pragma unroll
    for (int c = 0; c < N_CLS; c++) op[c] = acc[c];
}

// ---------------- launch ----------------
extern "C" void kernel_launch(void* const* d_in, const int* in_sizes, int n_in,
                              void* d_out, int out_size) {
    const float* x     = (const float*)d_in[0];
    const void*  ei    = d_in[1];
    const float* Wemb  = (const float*)d_in[2];
    const float* bemb  = (const float*)d_in[3];
    const float* Wgcn  = (const float*)d_in[4];
    const float* bgcn  = (const float*)d_in[5];
    const float* gamma = (const float*)d_in[6];
    const float* beta  = (const float*)d_in[7];
    const float* Wcls  = (const float*)d_in[8];
    const float* bcls  = (const float*)d_in[9];
    float* out = (float*)d_out;

    int n = in_sizes[0] / F_IN;      // 150000
    int e = in_sizes[1] / 2;         // 2400000

    k_zero<<<(n + 255) / 256, 256>>>((const long long*)ei, n);

    int quads = e >> 2;
    int buildBlocks = (quads + 255) / 256;
    int mlpBlocks = (n + 255) / 256;
    k_fused<<<buildBlocks + mlpBlocks, 256>>>(x, Wemb, bemb, Wgcn, ei, e, n, buildBlocks);
    if (e & 3) k_build_tail<<<1, 32>>>(ei, e, e & 3);

    k_scale<<<(n * 8 + 255) / 256, 256>>>(n);
    {
        int warps = (n + 3) / 4;
        k_gather<<<(warps * 32 + 255) / 256, 256>>>(bgcn, n);
    }
    k_cls<<<(n + 127) / 128, 128>>>(gamma, beta, Wcls, bcls, out, n);
}

// round 17
// speedup vs baseline: 1.0756x; 1.0036x over previous
#include <cuda_runtime.h>
#include <stdint.h>

#define N_MAXN 150000
#define E_MAXE 2400000
#define F_IN 22
#define HID 32
#define N_CLS 6
#define BN_EPS 1e-5f
#define MAXDEG 64
typedef unsigned long long ull;

// ---------------- packed f32x2 helpers (sm_100a) ----------------
__device__ __forceinline__ ull pack2(float lo, float hi) {
    ull r; asm("mov.b64 %0, {%1, %2};" : "=l"(r) : "f"(lo), "f"(hi)); return r;
}
__device__ __forceinline__ void unpack2(ull v, float& lo, float& hi) {
    asm("mov.b64 {%0, %1}, %2;" : "=f"(lo), "=f"(hi) : "l"(v));
}
__device__ __forceinline__ ull fma2(ull a, ull b, ull c) {
    ull d; asm("fma.rn.f32x2 %0, %1, %2, %3;" : "=l"(d) : "l"(a), "l"(b), "l"(c)); return d;
}
__device__ __forceinline__ ull add2(ull a, ull b) {
    ull d; asm("add.rn.f32x2 %0, %1, %2;" : "=l"(d) : "l"(a), "l"(b)); return d;
}

// ---------------- device scratch (no allocations allowed) ----------------
__device__ __align__(16) float g_hs[N_MAXN * HID];     // dis * ((relu(xWe+be))Wg)
__device__ __align__(16) float g_agg[N_MAXN * HID];
__device__ int   g_cnt[N_MAXN];
__device__ int   g_pad[(size_t)N_MAXN * MAXDEG];
__device__ float g_sum[HID];
__device__ float g_sumsq[HID];
__device__ int   g_is64;

// ---------------- zero counters + BN accum + dtype detection ----------------
__global__ void k_zero(const long long* __restrict__ ei, int n) {
    int i = blockIdx.x * blockDim.x + threadIdx.x;
    if (i < n) g_cnt[i] = 0;
    if (i < HID) { g_sum[i] = 0.0f; g_sumsq[i] = 0.0f; }
    if (blockIdx.x == 0 && threadIdx.x < 32) {
        int t = threadIdx.x;
        long long v0 = ei[t];
        long long v1 = ei[t + 32];
        int bad = (v0 < 0) | (v0 >= (long long)n) | (v1 < 0) | (v1 >= (long long)n);
        unsigned m = __ballot_sync(0xffffffffu, bad);
        if (t == 0) g_is64 = (m == 0u);
    }
}

// ---------------- build padded CSR (4 edges/thread, own kernel -> low regs) ----------------
__global__ void __launch_bounds__(256)
k_build(const void* __restrict__ ei, int e) {
    int i = blockIdx.x * 256 + threadIdx.x;
    int quads = e >> 2;
    if (i >= quads) return;
    int s[4], d[4];
    if (g_is64) {
        const longlong2* p = (const longlong2*)ei;
        longlong2 sv0 = p[2 * i], sv1 = p[2 * i + 1];
        const longlong2* pd = p + ((size_t)e >> 1);
        longlong2 dv0 = pd[2 * i], dv1 = pd[2 * i + 1];
        s[0] = (int)sv0.x; s[1] = (int)sv0.y; s[2] = (int)sv1.x; s[3] = (int)sv1.y;
        d[0] = (int)dv0.x; d[1] = (int)dv0.y; d[2] = (int)dv1.x; d[3] = (int)dv1.y;
    } else {
        const int4* p = (const int4*)ei;
        int4 sv = p[i];
        int4 dv = p[(size_t)(e >> 2) + i];
        s[0] = sv.x; s[1] = sv.y; s[2] = sv.z; s[3] = sv.w;
        d[0] = dv.x; d[1] = dv.y; d[2] = dv.z; d[3] = dv.w;
    }
#pragma unroll
    for (int k = 0; k < 4; k++) {
        int pos = atomicAdd(&g_cnt[d[k]], 1);
        if (pos < MAXDEG) g_pad[(size_t)d[k] * MAXDEG + pos] = s[k];
    }
}
// tail: leftover e % 4 edges (e=2.4M -> never launched; safety net)
__global__ void k_build_tail(const void* __restrict__ ei, int e, int r) {
    int k = threadIdx.x;
    if (k >= r) return;
    int i = e - 1 - k;
    int s, d;
    if (g_is64) {
        const long long* p = (const long long*)ei;
        s = (int)p[i]; d = (int)p[(size_t)e + i];
    } else {
        const int* p = (const int*)ei;
        s = p[i]; d = p[(size_t)e + i];
    }
    int pos = atomicAdd(&g_cnt[d], 1);
    if (pos < MAXDEG) g_pad[(size_t)d * MAXDEG + pos] = s;
}

// ---------------- fused MLP (f32x2, dis applied at store; proven 34.6us) ----------------
__global__ void __launch_bounds__(128)
k_mlp(const float* __restrict__ x, const float* __restrict__ Wemb,
      const float* __restrict__ bemb, const float* __restrict__ Wgcn, int n) {
    __shared__ __align__(16) float sWeT[HID * 24];   // [j][k], padded to 24
    __shared__ float sb[HID];
    __shared__ __align__(16) float sWg[HID * HID];   // [j][c]
    for (int i = threadIdx.x; i < F_IN * HID; i += blockDim.x) {
        int k = i / HID, j = i % HID;
        sWeT[j * 24 + k] = Wemb[i];
    }
    for (int i = threadIdx.x; i < HID; i += blockDim.x) {
        sWeT[i * 24 + 22] = 0.0f;
        sWeT[i * 24 + 23] = 0.0f;
    }
    for (int i = threadIdx.x; i < HID * HID; i += blockDim.x) sWg[i] = Wgcn[i];
    if (threadIdx.x < HID) sb[threadIdx.x] = bemb[threadIdx.x];
    __syncthreads();

    int node = blockIdx.x * blockDim.x + threadIdx.x;
    if (node >= n) return;

    float xr[F_IN];
    const float* xp = x + (size_t)node * F_IN;
#pragma unroll
    for (int k = 0; k < F_IN; k++) xr[k] = xp[k];
    ull xx[11];
#pragma unroll
    for (int q = 0; q < 11; q++) xx[q] = pack2(xr[2*q], xr[2*q+1]);

    ull acc2[16];
#pragma unroll
    for (int q = 0; q < 16; q++) acc2[q] = 0ull;

    for (int j = 0; j < HID; j++) {
        const ulonglong2* wr = (const ulonglong2*)(sWeT + j * 24);
        ulonglong2 wA = wr[0], wB = wr[1], wC = wr[2];
        ulonglong2 wD = wr[3], wE = wr[4], wF = wr[5];
        ull ta = fma2(xx[0], wA.x, 0ull);
        ull tb = fma2(xx[4], wC.x, 0ull);
        ull tc = fma2(xx[8], wE.x, 0ull);
        ta = fma2(xx[1], wA.y, ta);
        tb = fma2(xx[5], wC.y, tb);
        tc = fma2(xx[9], wE.y, tc);
        ta = fma2(xx[2], wB.x, ta);
        tb = fma2(xx[6], wD.x, tb);
        tc = fma2(xx[10], wF.x, tc);
        ta = fma2(xx[3], wB.y, ta);
        tb = fma2(xx[7], wD.y, tb);
        ull ts = add2(add2(ta, tb), tc);
        float lo, hi; unpack2(ts, lo, hi);
        float t = fmaxf(lo + hi + sb[j], 0.0f);
        ull tt = pack2(t, t);
        const ulonglong2* gr = (const ulonglong2*)(sWg + j * HID);
#pragma unroll
        for (int q = 0; q < 8; q++) {
            ulonglong2 g = gr[q];
            acc2[2*q]   = fma2(tt, g.x, acc2[2*q]);
            acc2[2*q+1] = fma2(tt, g.y, acc2[2*q+1]);
        }
    }

    float dis = rsqrtf((float)g_cnt[node] + 1.0f);
    float* hp = g_hs + (size_t)node * HID;
#pragma unroll
    for (int q = 0; q < 8; q++) {
        float a, b, c, d;
        unpack2(acc2[2*q], a, b);
        unpack2(acc2[2*q+1], c, d);
        ((float4*)hp)[q] = make_float4(a * dis, b * dis, c * dis, d * dis);
    }
}

// ---------------- gather (4 nodes/warp) + fused BN partial sums (R16) ----------------
__global__ void __launch_bounds__(256, 7)
k_gather(const float* __restrict__ bgcn, int n) {
    int warp = (blockIdx.x * 256 + threadIdx.x) >> 5;
    int lane = threadIdx.x & 31;
    int g = lane >> 3;           // group = node within warp
    int q = lane & 7;            // 16B feature slot
    int node = warp * 4 + g;
    bool valid = node < n;
    int nodec = valid ? node : (n - 1);

    int cnt = g_cnt[nodec];
    float dis = rsqrtf((float)cnt + 1.0f);
    int m = valid ? min(cnt, MAXDEG) : 0;

    const int* row = g_pad + (size_t)nodec * MAXDEG;

    float4 acc = make_float4(0.0f, 0.0f, 0.0f, 0.0f);
    if (valid) acc = ((const float4*)(g_hs + (size_t)nodec * HID))[q];

    int mmax = m;
#pragma unroll
    for (int o = 16; o; o >>= 1) mmax = max(mmax, __shfl_xor_sync(0xffffffffu, mmax, o));

    int grpbase = lane & 24;     // g*8
    int idx = 0;
    for (int j = 0; j < mmax; j += 4) {
        if ((j & 7) == 0) idx = row[j + q];
        int sA = __shfl_sync(0xffffffffu, idx, grpbase | ((j    ) & 7));
        int sB = __shfl_sync(0xffffffffu, idx, grpbase | ((j + 1) & 7));
        int sC = __shfl_sync(0xffffffffu, idx, grpbase | ((j + 2) & 7));
        int sD = __shfl_sync(0xffffffffu, idx, grpbase | ((j + 3) & 7));
        if (j < m) {
            float4 v = ((const float4*)(g_hs + (size_t)sA * HID))[q];
            acc.x += v.x; acc.y += v.y; acc.z += v.z; acc.w += v.w;
        }
        if (j + 1 < m) {
            float4 v = ((const float4*)(g_hs + (size_t)sB * HID))[q];
            acc.x += v.x; acc.y += v.y; acc.z += v.z; acc.w += v.w;
        }
        if (j + 2 < m) {
            float4 v = ((const float4*)(g_hs + (size_t)sC * HID))[q];
            acc.x += v.x; acc.y += v.y; acc.z += v.z; acc.w += v.w;
        }
        if (j + 3 < m) {
            float4 v = ((const float4*)(g_hs + (size_t)sD * HID))[q];
            acc.x += v.x; acc.y += v.y; acc.z += v.z; acc.w += v.w;
        }
    }

    float4 o = make_float4(0.0f, 0.0f, 0.0f, 0.0f);
    if (valid) {
        float4 bg = ((const float4*)bgcn)[q];
        o.x = fmaf(dis, acc.x, bg.x);
        o.y = fmaf(dis, acc.y, bg.y);
        o.z = fmaf(dis, acc.z, bg.z);
        o.w = fmaf(dis, acc.w, bg.w);
        ((float4*)(g_agg + (size_t)node * HID))[q] = o;
    }

    // fused BN partial reduction
    __shared__ float shs[8 * 128];
    __shared__ float shq[8 * 128];
    int wid = threadIdx.x >> 5;
    int base = wid * 128 + g * 32 + q * 4;
    shs[base + 0] = o.x; shs[base + 1] = o.y;
    shs[base + 2] = o.z; shs[base + 3] = o.w;
    shq[base + 0] = o.x * o.x; shq[base + 1] = o.y * o.y;
    shq[base + 2] = o.z * o.z; shq[base + 3] = o.w * o.w;
    __syncthreads();
    int t = threadIdx.x;
    if (t < 32) {
        float s = 0.0f;
#pragma unroll
        for (int w = 0; w < 8; w++) {
            s += shs[w * 128 +  0 + t] + shs[w * 128 + 32 + t]
               + shs[w * 128 + 64 + t] + shs[w * 128 + 96 + t];
        }
        atomicAdd(&g_sum[t], s);
    } else if (t < 64) {
        int c = t - 32;
        float s = 0.0f;
#pragma unroll
        for (int w = 0; w < 8; w++) {
            s += shq[w * 128 +  0 + c] + shq[w * 128 + 32 + c]
               + shq[w * 128 + 64 + c] + shq[w * 128 + 96 + c];
        }
        atomicAdd(&g_sumsq[c], s);
    }
}

// ---------------- classifier with inlined BN finalize ----------------
__global__ void __launch_bounds__(128)
k_cls(const float* __restrict__ gamma, const float* __restrict__ beta,
      const float* __restrict__ Wcls, const float* __restrict__ bcls,
      float* __restrict__ out, int n) {
    __shared__ float sW[HID * N_CLS];
    __shared__ float sbc[N_CLS];
    __shared__ float ssc[HID];
    __shared__ float ssh[HID];
    for (int i = threadIdx.x; i < HID * N_CLS; i += blockDim.x) sW[i] = Wcls[i];
    if (threadIdx.x < N_CLS) sbc[threadIdx.x] = bcls[threadIdx.x];
    if (threadIdx.x < HID) {
        int c = threadIdx.x;
        float inv_n = 1.0f / (float)n;
        float mean = g_sum[c] * inv_n;
        float var = g_sumsq[c] * inv_n - mean * mean;
        float sc = gamma[c] * rsqrtf(var + BN_EPS);
        ssc[c] = sc;
        ssh[c] = beta[c] - mean * sc;
    }
    __syncthreads();

    int node = blockIdx.x * blockDim.x + threadIdx.x;
    if (node >= n) return;

    float acc[N_CLS];
#pragma unroll
    for (int c = 0; c < N_CLS; c++) acc[c] = sbc[c];

    const float4* ap = (const float4*)(g_agg + (size_t)node * HID);
#pragma unroll
    for (int qq = 0; qq < HID / 4; qq++) {
        float4 v4 = ap[qq];
        float vv[4] = {v4.x, v4.y, v4.z, v4.w};
#pragma unroll
        for (int u = 0; u < 4; u++) {
            int j = qq * 4 + u;
            float v = fmaxf(fmaf(vv[u], ssc[j], ssh[j]), 0.0f);
#pragma unroll
            for (int c = 0; c < N_CLS; c++) acc[c] = fmaf(v, sW[j * N_CLS + c], acc[c]);
        }
    }
    float* op = out + (size_t)node * N_CLS;
#pragma unroll
    for (int c = 0; c < N_CLS; c++) op[c] = acc[c];
}

// ---------------- launch ----------------
extern "C" void kernel_launch(void* const* d_in, const int* in_sizes, int n_in,
                              void* d_out, int out_size) {
    const float* x     = (const float*)d_in[0];
    const void*  ei    = d_in[1];
    const float* Wemb  = (const float*)d_in[2];
    const float* bemb  = (const float*)d_in[3];
    const float* Wgcn  = (const float*)d_in[4];
    const float* bgcn  = (const float*)d_in[5];
    const float* gamma = (const float*)d_in[6];
    const float* beta  = (const float*)d_in[7];
    const float* Wcls  = (const float*)d_in[8];
    const float* bcls  = (const float*)d_in[9];
    float* out = (float*)d_out;

    int n = in_sizes[0] / F_IN;      // 150000
    int e = in_sizes[1] / 2;         // 2400000

    k_zero<<<(n + 255) / 256, 256>>>((const long long*)ei, n);

    int quads = e >> 2;
    k_build<<<(quads + 255) / 256, 256>>>(ei, e);
    if (e & 3) k_build_tail<<<1, 32>>>(ei, e, e & 3);

    k_mlp<<<(n + 127) / 128, 128>>>(x, Wemb, bemb, Wgcn, n);
    {
        int warps = (n + 3) / 4;
        k_gather<<<(warps * 32 + 255) / 256, 256>>>(bgcn, n);
    }
    k_cls<<<(n + 127) / 128, 128>>>(gamma, beta, Wcls, bcls, out, n);
}